// round 1
// baseline (speedup 1.0000x reference)
#include <cuda_runtime.h>
#include <cstdint>

// Problem constants
#define BB 4
#define FF 128        // feature = hidden size
#define TT 32000
#define KK 32
#define HH 64
#define GG 384        // 3*FF
#define BT (BB*TT)    // 128000

// ---------------- scratch (static device globals; allocation-free) ----------------
__device__ float g_seq[(size_t)BT * FF];          // [b*T+t][f]  (65.5 MB)
__device__ float g_X[(size_t)2 * BT * GG];        // [dir][b*T+t][g] (393 MB)

// ---------------- helpers ----------------
__device__ __forceinline__ unsigned long long ffma2(unsigned long long a,
                                                    unsigned long long b,
                                                    unsigned long long c) {
    unsigned long long d;
    asm("fma.rn.f32x2 %0, %1, %2, %3;" : "=l"(d) : "l"(a), "l"(b), "l"(c));
    return d;
}
__device__ __forceinline__ unsigned long long fadd2(unsigned long long a,
                                                    unsigned long long b) {
    unsigned long long d;
    asm("add.rn.f32x2 %0, %1, %2;" : "=l"(d) : "l"(a), "l"(b));
    return d;
}
__device__ __forceinline__ float lo32(unsigned long long v) {
    return __uint_as_float((unsigned)(v & 0xffffffffull));
}
__device__ __forceinline__ float hi32(unsigned long long v) {
    return __uint_as_float((unsigned)(v >> 32));
}
__device__ __forceinline__ unsigned long long pack2(float lo, float hi) {
    return (unsigned long long)__float_as_uint(lo) |
           ((unsigned long long)__float_as_uint(hi) << 32);
}
__device__ __forceinline__ float fsig(float x) {
    // safe: exp overflow -> inf -> rcp -> 0
    return __fdividef(1.f, 1.f + __expf(-x));
}
__device__ __forceinline__ float ftanh_(float x) {
    x = fminf(fmaxf(x, -15.f), 15.f);   // clamp: avoids exp overflow -> NaN
    float e = __expf(-2.f * x);
    return __fdividef(1.f - e, 1.f + e);
}

// ---------------- kernel 1: causal FIR conv (collapsed bank) + PReLU ----------------
// out[t] = PReLU( sum_{j=0..31} keff[j] * x[t-j] ), keff[j] = sum_h k[h][j]*kw[h][j]
#define CONV_TILE 2000
__global__ __launch_bounds__(256) void conv_prelu_kernel(
    const float* __restrict__ x, const float* __restrict__ kern,
    const float* __restrict__ kw, const float* __restrict__ pa) {
    __shared__ float keff_s[KK];
    __shared__ float xs[CONV_TILE + KK - 1];
    int bf = blockIdx.x;            // 0..511
    int b = bf >> 7, f = bf & 127;
    const float* xrow = x + (size_t)bf * TT;   // x layout [B,F,T]
    float a = *pa;

    if (threadIdx.x < KK) {
        float s = 0.f;
        #pragma unroll 8
        for (int h = 0; h < HH; h++)
            s += kern[h * KK + threadIdx.x] * kw[h * KK + threadIdx.x];
        keff_s[threadIdx.x] = s;
    }
    __syncthreads();
    float kr[KK];
    #pragma unroll
    for (int j = 0; j < KK; j++) kr[j] = keff_s[j];

    for (int t0 = 0; t0 < TT; t0 += CONV_TILE) {
        for (int i = threadIdx.x; i < CONV_TILE + KK - 1; i += 256) {
            int tt = t0 - (KK - 1) + i;
            xs[i] = (tt >= 0 && tt < TT) ? xrow[tt] : 0.f;
        }
        __syncthreads();
        for (int t = threadIdx.x; t < CONV_TILE; t += 256) {
            float acc = 0.f;
            #pragma unroll
            for (int j = 0; j < KK; j++)
                acc += kr[j] * xs[t + (KK - 1) - j];
            acc = (acc >= 0.f) ? acc : a * acc;
            g_seq[(size_t)(b * TT + t0 + t) * FF + f] = acc;
        }
        __syncthreads();
    }
}

// ---------------- kernel 2: X = seq @ W_ih^T + b_ih (both directions) ----------------
// grid: (M/64, 384/64, 2); 256 threads; 64x64 tile, TM=TN=4, full K=128 in 2 stages.
__global__ __launch_bounds__(256) void gemm_kernel(
    const float* __restrict__ Wf, const float* __restrict__ bf_,
    const float* __restrict__ Wb, const float* __restrict__ bb_) {
    __shared__ float As[64][65];   // [m][k], pad 65 for conflict-reduced scalar LDS
    __shared__ float Bs[64][65];   // [n][k]
    int dir = blockIdx.z;
    const float* W    = dir ? Wb  : Wf;
    const float* bias = dir ? bb_ : bf_;
    size_t m0 = (size_t)blockIdx.x * 64;
    int n0 = blockIdx.y * 64;
    int tid = threadIdx.x;
    int tx = tid & 15, ty = tid >> 4;

    float c[4][4];
    #pragma unroll
    for (int i = 0; i < 4; i++)
        #pragma unroll
        for (int j = 0; j < 4; j++) c[i][j] = 0.f;

    for (int kt = 0; kt < 128; kt += 64) {
        int r = tid >> 2;
        #pragma unroll
        for (int q = 0; q < 4; q++) {
            int kk = ((tid & 3) + q * 4) * 4;     // 0..60
            float4 va = *(const float4*)(g_seq + (m0 + r) * FF + kt + kk);
            As[r][kk + 0] = va.x; As[r][kk + 1] = va.y;
            As[r][kk + 2] = va.z; As[r][kk + 3] = va.w;
            float4 vb = *(const float4*)(W + (size_t)(n0 + r) * FF + kt + kk);
            Bs[r][kk + 0] = vb.x; Bs[r][kk + 1] = vb.y;
            Bs[r][kk + 2] = vb.z; Bs[r][kk + 3] = vb.w;
        }
        __syncthreads();
        #pragma unroll 4
        for (int k = 0; k < 64; k++) {
            float av[4], bv[4];
            #pragma unroll
            for (int i = 0; i < 4; i++) av[i] = As[ty * 4 + i][k];
            #pragma unroll
            for (int j = 0; j < 4; j++) bv[j] = Bs[tx * 4 + j][k];
            #pragma unroll
            for (int i = 0; i < 4; i++)
                #pragma unroll
                for (int j = 0; j < 4; j++) c[i][j] += av[i] * bv[j];
        }
        __syncthreads();
    }

    float b0 = bias[n0 + tx * 4 + 0], b1 = bias[n0 + tx * 4 + 1];
    float b2 = bias[n0 + tx * 4 + 2], b3 = bias[n0 + tx * 4 + 3];
    #pragma unroll
    for (int i = 0; i < 4; i++) {
        size_t m = m0 + ty * 4 + i;
        float4 v = make_float4(c[i][0] + b0, c[i][1] + b1,
                               c[i][2] + b2, c[i][3] + b3);
        *(float4*)(g_X + ((size_t)dir * BT + m) * GG + n0 + tx * 4) = v;
    }
}

// ---------------- kernel 3: recurrence. 8 CTAs (b,dir), 384 threads each ----------------
// Thread g owns gate row g: Whh[g][0..127] in 64 packed f32x2 registers.
// r/z threads (g<256) compute sigmoid and publish; n threads (g>=256) own h_j in a
// register, combine gates, update h, repack h pairs into smem, atomicAdd to out.
__global__ __launch_bounds__(384, 1) void gru_kernel(
    const float* __restrict__ Whh_f, const float* __restrict__ bhh_f,
    const float* __restrict__ Whh_b, const float* __restrict__ bhh_b,
    float* __restrict__ out) {
    __shared__ unsigned long long hp[64];   // packed h pairs
    __shared__ float gate[256];             // sigmoid(r), sigmoid(z)

    int cta = blockIdx.x;
    int dir = cta & 1, b = cta >> 1;
    const float* Whh = dir ? Whh_b : Whh_f;
    int g = threadIdx.x;
    float bh = (dir ? bhh_b : bhh_f)[g];

    unsigned long long w[64];
    {
        const unsigned long long* wrow =
            (const unsigned long long*)(Whh + (size_t)g * FF);
        #pragma unroll
        for (int k = 0; k < 64; k++) w[k] = wrow[k];
    }

    const float* Xbase = g_X + ((size_t)dir * BB + b) * (size_t)TT * GG;
    const float* xp = Xbase + (dir ? (size_t)(TT - 1) * GG : 0) + g;
    ptrdiff_t stepX = dir ? -GG : GG;
    float* orow = out + ((size_t)b * FF + (g & 127)) * TT;

    if (g < 64) hp[g] = 0ull;
    __syncthreads();

    float h_reg = 0.f;
    float xt = __ldg(xp);
    xp += stepX;

    for (int t = 0; t < TT; t++) {
        float xnext = 0.f;
        if (t + 1 < TT) xnext = __ldg(xp);
        xp += stepX;

        // dot(h, Whh_row[g]) with packed f32x2 FMAs
        unsigned long long a0 = 0, a1 = 0, a2 = 0, a3 = 0;
        #pragma unroll
        for (int k = 0; k < 64; k += 4) {
            a0 = ffma2(w[k + 0], hp[k + 0], a0);
            a1 = ffma2(w[k + 1], hp[k + 1], a1);
            a2 = ffma2(w[k + 2], hp[k + 2], a2);
            a3 = ffma2(w[k + 3], hp[k + 3], a3);
        }
        a0 = fadd2(a0, a1); a2 = fadd2(a2, a3); a0 = fadd2(a0, a2);
        float pre = lo32(a0) + hi32(a0) + bh;

        if (g < 256) gate[g] = fsig(xt + pre);   // r (g<128) / z (128..255)
        __syncthreads();                          // gates visible; h reads done
        if (g >= 256) {
            int j = g - 256;
            float r = gate[j];
            float z = gate[128 + j];
            float n = ftanh_(xt + r * pre);      // pre == gn for this thread
            float hnew = n + z * (h_reg - n);    // (1-z)*n + z*h
            h_reg = hnew;
            float hup = __shfl_down_sync(0xffffffff, hnew, 1);
            if (!(j & 1)) hp[j >> 1] = pack2(hnew, hup);
            int tt_ = dir ? (TT - 1 - t) : t;
            atomicAdd(orow + tt_, hnew);
        }
        __syncthreads();                          // hp ready for next step
        xt = xnext;
    }
}

// ---------------- launch ----------------
extern "C" void kernel_launch(void* const* d_in, const int* in_sizes, int n_in,
                              void* d_out, int out_size) {
    const float* x    = (const float*)d_in[0];
    const float* kern = (const float*)d_in[1];
    const float* kw   = (const float*)d_in[2];
    const float* pa   = (const float*)d_in[3];
    const float* Wihf = (const float*)d_in[4];
    const float* Whhf = (const float*)d_in[5];
    const float* bihf = (const float*)d_in[6];
    const float* bhhf = (const float*)d_in[7];
    const float* Wihb = (const float*)d_in[8];
    const float* Whhb = (const float*)d_in[9];
    const float* bihb = (const float*)d_in[10];
    const float* bhhb = (const float*)d_in[11];
    float* out = (float*)d_out;

    cudaMemsetAsync(out, 0, (size_t)out_size * sizeof(float));
    conv_prelu_kernel<<<BB * FF, 256>>>(x, kern, kw, pa);
    gemm_kernel<<<dim3(BT / 64, GG / 64, 2), 256>>>(Wihf, bihf, Wihb, bihb);
    gru_kernel<<<2 * BB, 384>>>(Whhf, bhhf, Whhb, bhhb, out);
}